// round 8
// baseline (speedup 1.0000x reference)
#include <cuda_runtime.h>

#define ROWS 48
#define ROW_ELEMS (512 * 512)                  // 262144 elements per (b,c) row
#define CHUNKS 32
#define CHUNK_ELEMS (ROW_ELEMS / CHUNKS)       // 8192
#define THREADS 256
#define VEC_PER_THREAD (CHUNK_ELEMS / 4 / THREADS)  // 8 float4 per thread

// Per-(row,chunk) partial min/max. Every slot is written unconditionally by
// minmax_kernel on every call -> no init kernel, no atomics, deterministic.
__device__ float g_pmin[ROWS][CHUNKS];
__device__ float g_pmax[ROWS][CHUNKS];

__global__ void __launch_bounds__(THREADS) minmax_kernel(const float4* __restrict__ in) {
    const int row = blockIdx.y;
    const int chunk = blockIdx.x;
    const long base4 = (long)row * (ROW_ELEMS / 4) + (long)chunk * (CHUNK_ELEMS / 4);
    const int tid = threadIdx.x;

    float mn = 3.402823466e+38f;
    float mx = -3.402823466e+38f;

#pragma unroll
    for (int k = 0; k < VEC_PER_THREAD; k++) {
        float4 v = in[base4 + k * THREADS + tid];
        mn = fminf(mn, fminf(fminf(v.x, v.y), fminf(v.z, v.w)));
        mx = fmaxf(mx, fmaxf(fmaxf(v.x, v.y), fmaxf(v.z, v.w)));
    }

#pragma unroll
    for (int o = 16; o > 0; o >>= 1) {
        mn = fminf(mn, __shfl_xor_sync(0xffffffffu, mn, o));
        mx = fmaxf(mx, __shfl_xor_sync(0xffffffffu, mx, o));
    }

    __shared__ float smn[THREADS / 32];
    __shared__ float smx[THREADS / 32];
    if ((tid & 31) == 0) {
        smn[tid >> 5] = mn;
        smx[tid >> 5] = mx;
    }
    __syncthreads();

    if (tid == 0) {
        float bmn = smn[0], bmx = smx[0];
#pragma unroll
        for (int w = 1; w < THREADS / 32; w++) {
            bmn = fminf(bmn, smn[w]);
            bmx = fmaxf(bmx, smx[w]);
        }
        g_pmin[row][chunk] = bmn;
        g_pmax[row][chunk] = bmx;
    }
}

// Reference-exact bound: b_j = fl32( mn + fl32( d * (j/16) ) ), j/16 exact.
// Exact-rounding intrinsics block fma contraction (must match JAX bit-for-bit).
__device__ __forceinline__ float bound_j(float mn, float d, int j) {
    return __fadd_rn(mn, __fmul_rn(d, (float)j * 0.0625f));
}
// Reference-exact mid: m_j = fl32( 0.5 * fl32( b_j + b_{j+1} ) ).
__device__ __forceinline__ float mid_j(float mn, float d, int j) {
    return __fmul_rn(0.5f, __fadd_rn(bound_j(mn, d, j), bound_j(mn, d, j + 1)));
}

__global__ void __launch_bounds__(THREADS) quantize_kernel(const float4* __restrict__ in,
                                                           float4* __restrict__ out) {
    const int row = blockIdx.y;
    const int chunk = blockIdx.x;
    const long base4 = (long)row * (ROW_ELEMS / 4) + (long)chunk * (CHUNK_ELEMS / 4);
    const int tid = threadIdx.x;
    const int lane = tid & 31;

    // One warp reduces the 32 partials; broadcast via 2 smem floats.
    __shared__ float s_mn, s_mx;
    if (tid < 32) {
        float v1 = g_pmin[row][tid];
        float v2 = g_pmax[row][tid];
#pragma unroll
        for (int o = 16; o > 0; o >>= 1) {
            v1 = fminf(v1, __shfl_xor_sync(0xffffffffu, v1, o));
            v2 = fmaxf(v2, __shfl_xor_sync(0xffffffffu, v2, o));
        }
        if (tid == 0) { s_mn = v1; s_mx = v2; }
    }
    __syncthreads();

    const float mn = s_mn;
    const float mx = s_mx;
    const float d = __fadd_rn(mx, -mn);  // mx >= mn

    // Degenerate test, matching float32 reference arithmetic:
    // robust_eps = 4 * FLT_EPSILON; deg = d <= robust_eps + 1e-5 * |mx|
    const float thresh = __fadd_rn(4.76837158203125e-07f, __fmul_rn(1e-5f, fabsf(mx)));
    if (d <= thresh) {
        float4 q;
        q.x = q.y = q.z = q.w = mn;
#pragma unroll
        for (int k = 0; k < VEC_PER_THREAD; k++) {
            out[base4 + k * THREADS + tid] = q;
        }
        return;
    }

    // One-probe lookup table, lane-replicated (16B/lane -> LDS.128 conflict-free).
    // tbl[idx][lane] = (probe = b_idx, lo = m_{idx-1}, hi = m_idx, pad)
    //   idx = floor((x-mn)*scale + 0.5) clamped to [0,16]; provably in
    //   {r_true, r_true+1}, so the probe resolves exactly:
    //     x >= b_idx  -> region idx     -> hi = m_idx
    //     x <  b_idx  -> region idx-1   -> lo = m_{idx-1}
    //   idx=16: probe=+INF (never promote past 15), lo = m_15.
    //   idx=0:  probe=b_0=mn <= x always -> hi = m_0.
    __shared__ float4 tbl[17 * 32];
    for (int s = tid; s < 17 * 32; s += THREADS) {
        int e = s >> 5;
        float4 t;
        t.x = (e <= 15) ? bound_j(mn, d, e) : __int_as_float(0x7f800000);  // probe
        t.y = mid_j(mn, d, (e > 0) ? (e - 1) : 0);                          // lo
        t.z = mid_j(mn, d, (e <= 15) ? e : 15);                             // hi
        t.w = 0.0f;
        tbl[s] = t;
    }
    __syncthreads();

    const float scale = 16.0f / d;
    const float bias = __fmaf_rn(-mn, scale, 0.5f);  // (x-mn)*scale + 0.5 in one FFMA
    const float4* tl = tbl + lane;                   // per-lane base, stride 32 entries

#pragma unroll
    for (int k = 0; k < VEC_PER_THREAD; k++) {
        float4 v = in[base4 + k * THREADS + tid];
        float xv[4] = {v.x, v.y, v.z, v.w};
        float qv[4];
#pragma unroll
        for (int e = 0; e < 4; e++) {
            float x = xv[e];
            int idx = __float2int_rd(__fmaf_rn(x, scale, bias));
            idx = min(max(idx, 0), 16);
            float4 t = tl[idx << 5];
            qv[e] = (x >= t.x) ? t.z : t.y;
        }
        float4 q;
        q.x = qv[0]; q.y = qv[1]; q.z = qv[2]; q.w = qv[3];
        out[base4 + k * THREADS + tid] = q;
    }
}

extern "C" void kernel_launch(void* const* d_in, const int* in_sizes, int n_in,
                              void* d_out, int out_size) {
    const float4* in = (const float4*)d_in[0];
    float4* out = (float4*)d_out;

    dim3 grid(CHUNKS, ROWS);
    minmax_kernel<<<grid, THREADS>>>(in);
    quantize_kernel<<<grid, THREADS>>>(in, out);
}

// round 9
// speedup vs baseline: 1.1078x; 1.1078x over previous
#include <cuda_runtime.h>

#define ROWS 48
#define ROW_ELEMS (512 * 512)                  // 262144 elements per (b,c) row
#define CHUNKS 32
#define CHUNK_ELEMS (ROW_ELEMS / CHUNKS)       // 8192
#define THREADS 256
#define VEC_PER_THREAD (CHUNK_ELEMS / 4 / THREADS)  // 8 float4 per thread

// Per-(row,chunk) partial min/max. Every slot is written unconditionally by
// minmax_kernel on every call -> no init kernel, no atomics, deterministic.
__device__ float g_pmin[ROWS][CHUNKS];
__device__ float g_pmax[ROWS][CHUNKS];

__global__ void __launch_bounds__(THREADS) minmax_kernel(const float4* __restrict__ in) {
    const int row = blockIdx.y;
    const int chunk = blockIdx.x;
    const long base4 = (long)row * (ROW_ELEMS / 4) + (long)chunk * (CHUNK_ELEMS / 4);
    const int tid = threadIdx.x;

    float mn = 3.402823466e+38f;
    float mx = -3.402823466e+38f;

#pragma unroll
    for (int k = 0; k < VEC_PER_THREAD; k++) {
        float4 v = in[base4 + k * THREADS + tid];
        mn = fminf(mn, fminf(fminf(v.x, v.y), fminf(v.z, v.w)));
        mx = fmaxf(mx, fmaxf(fmaxf(v.x, v.y), fmaxf(v.z, v.w)));
    }

#pragma unroll
    for (int o = 16; o > 0; o >>= 1) {
        mn = fminf(mn, __shfl_xor_sync(0xffffffffu, mn, o));
        mx = fmaxf(mx, __shfl_xor_sync(0xffffffffu, mx, o));
    }

    __shared__ float smn[THREADS / 32];
    __shared__ float smx[THREADS / 32];
    if ((tid & 31) == 0) {
        smn[tid >> 5] = mn;
        smx[tid >> 5] = mx;
    }
    __syncthreads();

    if (tid == 0) {
        float bmn = smn[0], bmx = smx[0];
#pragma unroll
        for (int w = 1; w < THREADS / 32; w++) {
            bmn = fminf(bmn, smn[w]);
            bmx = fmaxf(bmx, smx[w]);
        }
        g_pmin[row][chunk] = bmn;
        g_pmax[row][chunk] = bmx;
    }
}

// Reference-exact bound: b_j = fl32( mn + fl32( d * (j/16) ) ), j/16 exact.
// Exact-rounding intrinsics block fma contraction (must match JAX bit-for-bit).
__device__ __forceinline__ float bound_j(float mn, float d, int j) {
    return __fadd_rn(mn, __fmul_rn(d, (float)j * 0.0625f));
}
// Reference-exact mid: m_j = fl32( 0.5 * fl32( b_j + b_{j+1} ) ).
__device__ __forceinline__ float mid_j(float mn, float d, int j) {
    return __fmul_rn(0.5f, __fadd_rn(bound_j(mn, d, j), bound_j(mn, d, j + 1)));
}

__global__ void __launch_bounds__(THREADS) quantize_kernel(const float4* __restrict__ in,
                                                           float4* __restrict__ out) {
    const int row = blockIdx.y;
    const int chunk = blockIdx.x;
    const long base4 = (long)row * (ROW_ELEMS / 4) + (long)chunk * (CHUNK_ELEMS / 4);
    const int tid = threadIdx.x;
    const int lane = tid & 31;

    // One warp reduces the 32 partials; broadcast via 2 smem floats.
    __shared__ float s_mn, s_mx;
    if (tid < 32) {
        float v1 = g_pmin[row][tid];
        float v2 = g_pmax[row][tid];
#pragma unroll
        for (int o = 16; o > 0; o >>= 1) {
            v1 = fminf(v1, __shfl_xor_sync(0xffffffffu, v1, o));
            v2 = fmaxf(v2, __shfl_xor_sync(0xffffffffu, v2, o));
        }
        if (tid == 0) { s_mn = v1; s_mx = v2; }
    }
    __syncthreads();

    const float mn = s_mn;
    const float mx = s_mx;
    const float d = __fadd_rn(mx, -mn);  // mx >= mn

    // Degenerate test, matching float32 reference arithmetic:
    // robust_eps = 4 * FLT_EPSILON; deg = d <= robust_eps + 1e-5 * |mx|
    const float thresh = __fadd_rn(4.76837158203125e-07f, __fmul_rn(1e-5f, fabsf(mx)));
    if (d <= thresh) {
        float4 q;
        q.x = q.y = q.z = q.w = mn;
#pragma unroll
        for (int k = 0; k < VEC_PER_THREAD; k++) {
            out[base4 + k * THREADS + tid] = q;
        }
        return;
    }

    // One-probe lookup, split tables, lane-replicated -> conflict-free:
    //   tp[idx][lane] : probe = b_idx           (LDS.32, 1 crossbar cyc)
    //   tm[idx][lane] : (lo, hi) = (m_{idx-1}, m_idx)  (LDS.64, 2 cyc)
    // idx = floor((x-mn)*scale + 0.5) clamped to [0,16]; provably in
    // {r_true, r_true+1}, so one compare resolves exactly:
    //   x >= b_idx -> region idx   -> hi = m_idx
    //   x <  b_idx -> region idx-1 -> lo = m_{idx-1}
    // idx=16: probe=+INF (never promote past 15), lo = m_15.
    // idx=0:  probe=b_0=mn <= x always -> hi = m_0.
    __shared__ float  tp[17 * 32];
    __shared__ float2 tm[17 * 32];
    for (int s = tid; s < 17 * 32; s += THREADS) {
        int e = s >> 5;
        tp[s] = (e <= 15) ? bound_j(mn, d, e) : __int_as_float(0x7f800000);
        float2 t;
        t.x = mid_j(mn, d, (e > 0) ? (e - 1) : 0);   // lo
        t.y = mid_j(mn, d, (e <= 15) ? e : 15);      // hi
        tm[s] = t;
    }
    __syncthreads();

    const float scale = 16.0f / d;
    const float bias = __fmaf_rn(-mn, scale, 0.5f);  // (x-mn)*scale + 0.5 in one FFMA
    const float* tpl = tp + lane;
    const float2* tml = tm + lane;

#pragma unroll
    for (int k = 0; k < VEC_PER_THREAD; k++) {
        float4 v = in[base4 + k * THREADS + tid];
        float xv[4] = {v.x, v.y, v.z, v.w};
        float qv[4];
#pragma unroll
        for (int e = 0; e < 4; e++) {
            float x = xv[e];
            int idx = __float2int_rd(__fmaf_rn(x, scale, bias));
            idx = min(max(idx, 0), 16);
            float probe = tpl[idx << 5];   // independent loads, same idx ->
            float2 mids = tml[idx << 5];   // issue back-to-back, one latency hop
            qv[e] = (x >= probe) ? mids.y : mids.x;
        }
        float4 q;
        q.x = qv[0]; q.y = qv[1]; q.z = qv[2]; q.w = qv[3];
        out[base4 + k * THREADS + tid] = q;
    }
}

extern "C" void kernel_launch(void* const* d_in, const int* in_sizes, int n_in,
                              void* d_out, int out_size) {
    const float4* in = (const float4*)d_in[0];
    float4* out = (float4*)d_out;

    dim3 grid(CHUNKS, ROWS);
    minmax_kernel<<<grid, THREADS>>>(in);
    quantize_kernel<<<grid, THREADS>>>(in, out);
}

// round 11
// speedup vs baseline: 1.1094x; 1.0014x over previous
#include <cuda_runtime.h>

#define ROWS 48
#define ROW_ELEMS (512 * 512)                  // 262144 elements per (b,c) row
#define CHUNKS 32
#define CHUNK_ELEMS (ROW_ELEMS / CHUNKS)       // 8192
#define THREADS 256
#define VEC_PER_THREAD (CHUNK_ELEMS / 4 / THREADS)  // 8 float4 per thread
#define GROUP 4                                      // prefetch group size (MLP)

// Per-(row,chunk) partial min/max. Every slot is written unconditionally by
// minmax_kernel on every call -> no init kernel, no atomics, deterministic.
__device__ float g_pmin[ROWS][CHUNKS];
__device__ float g_pmax[ROWS][CHUNKS];

__global__ void __launch_bounds__(THREADS) minmax_kernel(const float4* __restrict__ in) {
    const int row = blockIdx.y;
    const int chunk = blockIdx.x;
    const long base4 = (long)row * (ROW_ELEMS / 4) + (long)chunk * (CHUNK_ELEMS / 4);
    const int tid = threadIdx.x;

    float mn = 3.402823466e+38f;
    float mx = -3.402823466e+38f;

#pragma unroll
    for (int k = 0; k < VEC_PER_THREAD; k++) {
        float4 v = in[base4 + k * THREADS + tid];
        mn = fminf(mn, fminf(fminf(v.x, v.y), fminf(v.z, v.w)));
        mx = fmaxf(mx, fmaxf(fmaxf(v.x, v.y), fmaxf(v.z, v.w)));
    }

#pragma unroll
    for (int o = 16; o > 0; o >>= 1) {
        mn = fminf(mn, __shfl_xor_sync(0xffffffffu, mn, o));
        mx = fmaxf(mx, __shfl_xor_sync(0xffffffffu, mx, o));
    }

    __shared__ float smn[THREADS / 32];
    __shared__ float smx[THREADS / 32];
    if ((tid & 31) == 0) {
        smn[tid >> 5] = mn;
        smx[tid >> 5] = mx;
    }
    __syncthreads();

    if (tid == 0) {
        float bmn = smn[0], bmx = smx[0];
#pragma unroll
        for (int w = 1; w < THREADS / 32; w++) {
            bmn = fminf(bmn, smn[w]);
            bmx = fmaxf(bmx, smx[w]);
        }
        g_pmin[row][chunk] = bmn;
        g_pmax[row][chunk] = bmx;
    }
}

// Reference-exact bound: b_j = fl32( mn + fl32( d * (j/16) ) ), j/16 exact.
// Exact-rounding intrinsics block fma contraction (must match JAX bit-for-bit).
__device__ __forceinline__ float bound_j(float mn, float d, int j) {
    return __fadd_rn(mn, __fmul_rn(d, (float)j * 0.0625f));
}

__global__ void __launch_bounds__(THREADS) quantize_kernel(const float4* __restrict__ in,
                                                           float4* __restrict__ out) {
    const int row = blockIdx.y;
    const int chunk = blockIdx.x;
    const long base4 = (long)row * (ROW_ELEMS / 4) + (long)chunk * (CHUNK_ELEMS / 4);
    const int tid = threadIdx.x;
    const int lane = tid & 31;

    // One warp reduces the 32 partials; broadcast via 2 smem floats.
    __shared__ float s_mn, s_mx;
    if (tid < 32) {
        float v1 = g_pmin[row][tid];
        float v2 = g_pmax[row][tid];
#pragma unroll
        for (int o = 16; o > 0; o >>= 1) {
            v1 = fminf(v1, __shfl_xor_sync(0xffffffffu, v1, o));
            v2 = fmaxf(v2, __shfl_xor_sync(0xffffffffu, v2, o));
        }
        if (tid == 0) { s_mn = v1; s_mx = v2; }
    }
    __syncthreads();

    const float mn = s_mn;
    const float mx = s_mx;
    const float d = __fadd_rn(mx, -mn);  // mx >= mn

    // Degenerate test, matching float32 reference arithmetic:
    // robust_eps = 4 * FLT_EPSILON; deg = d <= robust_eps + 1e-5 * |mx|
    const float thresh = __fadd_rn(4.76837158203125e-07f, __fmul_rn(1e-5f, fabsf(mx)));
    if (d <= thresh) {
        float4 q;
        q.x = q.y = q.z = q.w = mn;
#pragma unroll
        for (int k = 0; k < VEC_PER_THREAD; k++) {
            out[base4 + k * THREADS + tid] = q;
        }
        return;
    }

    // Lane-replicated tables: index [j*32 + lane] -> bank == lane, conflict-free.
    __shared__ float sb[17 * 32];  // bounds b_0..b_16 (sb[0]=mn exactly)
    __shared__ float sm[16 * 32];  // mids m_0..m_15 = fl(0.5 * fl(b_j + b_{j+1}))
    for (int s = tid; s < 17 * 32; s += THREADS) {
        sb[s] = bound_j(mn, d, s >> 5);
    }
    for (int s = tid; s < 16 * 32; s += THREADS) {
        int j = s >> 5;
        sm[s] = __fmul_rn(0.5f, __fadd_rn(bound_j(mn, d, j), bound_j(mn, d, j + 1)));
    }
    __syncthreads();

    const float scale = 16.0f / d;           // estimate only; fixup makes it exact
    const float bias = -mn * scale;          // (x - mn)*scale as one FFMA

    // Software-pipelined: front-batch GROUP LDG.128s (MLP=4), process group g
    // while group g+1 is in flight. Hides the ~234-cyc L2-hit latency.
    float4 cur[GROUP], nxt[GROUP];
#pragma unroll
    for (int j = 0; j < GROUP; j++) {
        cur[j] = in[base4 + j * THREADS + tid];
    }

#pragma unroll
    for (int g = 0; g < VEC_PER_THREAD / GROUP; g++) {
        // Prefetch next group (except on last iteration).
        if (g + 1 < VEC_PER_THREAD / GROUP) {
#pragma unroll
            for (int j = 0; j < GROUP; j++) {
                nxt[j] = in[base4 + ((g + 1) * GROUP + j) * THREADS + tid];
            }
        }

#pragma unroll
        for (int j = 0; j < GROUP; j++) {
            float4 v = cur[j];
            float xv[4] = {v.x, v.y, v.z, v.w};
            float qv[4];
#pragma unroll
            for (int e = 0; e < 4; e++) {
                float x = xv[e];
                int r = __float2int_rz(__fmaf_rn(x, scale, bias));
                r = min(max(r, 0), 15);
                // Both probes at the SAME r -> the two LDS are independent.
                // Estimate provably within +-1 region; up/down mutually exclusive:
                //   up:   b_{r+1} <= x  (r=15/x~mx spurious fire clamped by min)
                //   down: b_r     >  x  (never fires at r=0 since sb[0]=mn <= x)
                int up = (sb[((r + 1) << 5) + lane] <= x) ? 1 : 0;
                int down = (sb[(r << 5) + lane] > x) ? 1 : 0;
                r = min(r + up - down, 15);
                qv[e] = sm[(r << 5) + lane];
            }
            float4 q;
            q.x = qv[0]; q.y = qv[1]; q.z = qv[2]; q.w = qv[3];
            out[base4 + (g * GROUP + j) * THREADS + tid] = q;
        }

#pragma unroll
        for (int j = 0; j < GROUP; j++) {
            cur[j] = nxt[j];
        }
    }
}

extern "C" void kernel_launch(void* const* d_in, const int* in_sizes, int n_in,
                              void* d_out, int out_size) {
    const float4* in = (const float4*)d_in[0];
    float4* out = (float4*)d_out;

    dim3 grid(CHUNKS, ROWS);
    minmax_kernel<<<grid, THREADS>>>(in);
    quantize_kernel<<<grid, THREADS>>>(in, out);
}